// round 17
// baseline (speedup 1.0000x reference)
#include <cuda_runtime.h>
#include <cuda_fp16.h>
#include <cstdint>
#include <math.h>

constexpr int kT = 4, kB = 8, kC = 384, kN = 1024;
constexpr int kBCN  = kB * kC * kN;
constexpr int kTBCN = kT * kBCN;
constexpr float kEPS = 1e-5f;
constexpr int kWelems = kC * kC;            // 147456
constexpr float kLoScale = 1.0f / 4096.0f;

// ---------------- device scratch ----------------
__device__ __half g_wqkv[6 * kWelems];      // [branch*2+split][m][k]  (hi, lo*4096)
__device__ __half g_wp[2 * kWelems];        // [split][m][k] (proj uses hi only)
__device__ __half g_sx[kTBCN];              // input spikes  [t][b][n][c]
__device__ __half g_qb[kTBCN];              // q spikes      [t][b][n][c]
__device__ uint32_t g_kbm[kT * kB * kC * (kN / 32)];  // k spike bitmask [t][b][c][n/32]
__device__ uint32_t g_vbm[kT * kB * kC * (kN / 32)];  // v spike bitmask
__device__ __half g_kvsh[kT * kB * kC];     // kv spikes (fp16)

// ---------------- helpers ----------------
__device__ __forceinline__ uint32_t smem_u32(const void* p) {
    uint32_t a;
    asm("{ .reg .u64 t; cvta.to.shared.u64 t, %1; cvt.u32.u64 %0, t; }" : "=r"(a) : "l"(p));
    return a;
}
__device__ __forceinline__ void cp16(uint32_t dst, const void* src) {
    asm volatile("cp.async.cg.shared.global [%0], [%1], 16;" :: "r"(dst), "l"(src));
}
__device__ __forceinline__ void ldm_x4(uint32_t* r, uint32_t addr) {
    asm volatile("ldmatrix.sync.aligned.m8n8.x4.shared.b16 {%0,%1,%2,%3}, [%4];"
                 : "=r"(r[0]), "=r"(r[1]), "=r"(r[2]), "=r"(r[3]) : "r"(addr));
}
__device__ __forceinline__ void mma16816(float* c, const uint32_t* a, uint32_t b0, uint32_t b1) {
    asm volatile("mma.sync.aligned.m16n8k16.row.col.f32.f16.f16.f32 "
                 "{%0,%1,%2,%3}, {%4,%5,%6,%7}, {%8,%9}, {%0,%1,%2,%3};"
                 : "+f"(c[0]), "+f"(c[1]), "+f"(c[2]), "+f"(c[3])
                 : "r"(a[0]), "r"(a[1]), "r"(a[2]), "r"(a[3]), "r"(b0), "r"(b1));
}
// fp16-accumulate variant
__device__ __forceinline__ void mma16816h(uint32_t* c, const uint32_t* a, uint32_t b0, uint32_t b1) {
    asm volatile("mma.sync.aligned.m16n8k16.row.col.f16.f16.f16.f16 "
                 "{%0,%1}, {%2,%3,%4,%5}, {%6,%7}, {%0,%1};"
                 : "+r"(c[0]), "+r"(c[1])
                 : "r"(a[0]), "r"(a[1]), "r"(a[2]), "r"(a[3]), "r"(b0), "r"(b1));
}
__device__ __forceinline__ uint32_t hmul2u(uint32_t a, uint32_t b) {
    __half2 r = __hmul2(*(__half2*)&a, *(__half2*)&b);
    return *(uint32_t*)&r;
}

// GEMM tiling: 128(M) x 64(N) x 32(K), 8 warps (4m x 2n).
constexpr int BM = 128, BN = 64, BK = 32;
constexpr int PITCH = 40;
constexpr int A_ELEMS = 2 * BM * PITCH;          // 10240
constexpr int B_ELEMS = BN * PITCH;              // 2560
constexpr int STAGE_ELEMS = A_ELEMS + B_ELEMS;   // 12800
constexpr int STAGE_BYTES = STAGE_ELEMS * 2;     // 25600
constexpr int VST_OFF  = 3 * STAGE_BYTES;        // 76800
constexpr int FSMEM    = VST_OFF + 256 * 32 * 4; // 109568
constexpr int QPITCH = 136;
constexpr int KVP    = 72;

// proj kernel: 3 stages, hi split only
constexpr int PJA_ELEMS = BM * PITCH;                 // 5120
constexpr int PJSTAGE_ELEMS = PJA_ELEMS + B_ELEMS;    // 7680
constexpr int PJSTAGE_BYTES = PJSTAGE_ELEMS * 2;      // 15360
constexpr int PJSMEM = 3 * PJSTAGE_BYTES;             // 46080

// ---------------------------------------------------------------------------
// K1 (merged): z<8 -> LIF on x for batch z; z>=8 -> weight split blocks.
// ---------------------------------------------------------------------------
__global__ void lif_x_split_kernel(const float* __restrict__ x,
                                   const float* __restrict__ qw, const float* __restrict__ kw,
                                   const float* __restrict__ vw, const float* __restrict__ pw) {
    if (blockIdx.z >= kB) {
        int bidx = (blockIdx.z - kB) * (gridDim.y * gridDim.x) + blockIdx.y * gridDim.x + blockIdx.x;
        int idx = bidx * 256 + threadIdx.x;
        if (idx >= 4 * kWelems) return;
        int mat = idx / kWelems;
        int e = idx - mat * kWelems;
        const float* src = (mat == 0) ? qw : (mat == 1) ? kw : (mat == 2) ? vw : pw;
        float w = src[e];
        __half h = __float2half_rn(w);
        __half l = __float2half_rn((w - __half2float(h)) * 4096.0f);
        if (mat < 3) {
            g_wqkv[(mat * 2 + 0) * kWelems + e] = h;
            g_wqkv[(mat * 2 + 1) * kWelems + e] = l;
        } else {
            g_wp[0 * kWelems + e] = h;
            g_wp[1 * kWelems + e] = l;
        }
        return;
    }
    __shared__ __half sm[32][36];
    const int lane = threadIdx.x & 31, wid = threadIdx.x >> 5;
    const int n0 = blockIdx.x * 32, c0 = blockIdx.y * 32, b = blockIdx.z;
    float v[4] = {0.f, 0.f, 0.f, 0.f};
    for (int t = 0; t < kT; t++) {
#pragma unroll
        for (int j = 0; j < 4; j++) {
            int c = c0 + wid * 4 + j;
            float xv = x[((size_t)((t * kB + b) * kC + c)) * kN + n0 + lane];
            v[j] += (xv - v[j]) * 0.5f;
            float s = 0.f;
            if (v[j] >= 0.5f) { s = 1.f; v[j] = 0.f; }
            sm[lane][wid * 4 + j] = __float2half(s);
        }
        __syncthreads();
        int nr = wid * 4 + (lane >> 3);
        int cw = (lane & 7) * 4;
        uint2 val = *(const uint2*)&sm[nr][cw];
        *(uint2*)&g_sx[((size_t)((t * kB + b) * kN + n0 + nr)) * kC + c0 + cw] = val;
        __syncthreads();
    }
}

// ---------------------------------------------------------------------------
// FUSED QKV (identical to R16).
// ---------------------------------------------------------------------------
__global__ __launch_bounds__(256, 2) void fused_qkv_kernel(
    const float* __restrict__ qg, const float* __restrict__ qbe, const float* __restrict__ qm, const float* __restrict__ qva,
    const float* __restrict__ kg, const float* __restrict__ kbe, const float* __restrict__ km, const float* __restrict__ kva,
    const float* __restrict__ vg, const float* __restrict__ vbe, const float* __restrict__ vm, const float* __restrict__ vva)
{
    extern __shared__ char dynsm[];
    const uint32_t shb = smem_u32(dynsm);
    float* vsm = (float*)(dynsm + VST_OFF);
    __half* stg = (__half*)(dynsm + STAGE_BYTES);

    const int tid = threadIdx.x, wid = tid >> 5, lane = tid & 31;
    const int b = blockIdx.z;
    const int yy = blockIdx.y;
    const int p = (yy >= 6) ? 2 : ((yy >= 3) ? 1 : 0);
    const int mtile = yy - p * 3;
    const int m0 = mtile * BM, n0 = blockIdx.x * BN;

    const __half* Abase = g_wqkv + (size_t)(p * 2) * kWelems;
    const int mw = wid >> 1, nw = wid & 1;
    const int gr = lane >> 2, gc = (lane & 3) * 2;
    const int ldrow = lane & 15, ldhalf = lane >> 4;

    const float *G, *Be, *Mn, *Va;
    if (p == 0)      { G = qg; Be = qbe; Mn = qm; Va = qva; }
    else if (p == 1) { G = kg; Be = kbe; Mn = km; Va = kva; }
    else             { G = vg; Be = vbe; Mn = vm; Va = vva; }
    float scv[2][2], mnv[2][2], bev[2][2];
#pragma unroll
    for (int mi = 0; mi < 2; mi++)
#pragma unroll
        for (int half = 0; half < 2; half++) {
            int cc = m0 + mw * 32 + mi * 16 + half * 8 + gr;
            scv[mi][half] = G[cc] / sqrtf(Va[cc] + kEPS);
            mnv[mi][half] = Mn[cc];
            bev[mi][half] = Be[cc];
        }

#pragma unroll
    for (int j = 0; j < 32; j++) vsm[j * 256 + tid] = 0.f;

    auto load_chunk = [&](int t, int ck, int st) {
        const uint32_t sb = shb + st * STAGE_BYTES;
        const int k0 = ck * BK;
#pragma unroll
        for (int it = 0; it < 4; it++) {
            int i = it * 256 + tid;
            int sp = i >> 9, rem = i & 511, r = rem >> 2, kq = rem & 3;
            cp16(sb + ((sp * BM + r) * PITCH + kq * 8) * 2,
                 Abase + (size_t)sp * kWelems + (size_t)(m0 + r) * kC + k0 + kq * 8);
        }
        {
            int r = tid >> 2, kq = tid & 3;
            cp16(sb + (A_ELEMS + r * PITCH + kq * 8) * 2,
                 g_sx + ((size_t)(t * kB + b) * kN + n0 + r) * kC + k0 + kq * 8);
        }
        asm volatile("cp.async.commit_group;");
    };

    load_chunk(0, 0, 0);
    load_chunk(0, 1, 1);

    for (int t = 0; t < kT; t++) {
        float acch[2][4][4];
        uint32_t accl[2][4][2];
#pragma unroll
        for (int i = 0; i < 2; i++)
#pragma unroll
            for (int j = 0; j < 4; j++) {
#pragma unroll
                for (int q = 0; q < 4; q++) acch[i][j][q] = 0.f;
                accl[i][j][0] = 0u; accl[i][j][1] = 0u;
            }

        for (int cch = 0; cch < 12; cch++) {
            if (t == kT - 1 && cch == 11) {
                asm volatile("cp.async.wait_group 0;");
            } else {
                asm volatile("cp.async.wait_group 1;");
            }
            __syncthreads();
            if (cch <= 9) {
                load_chunk(t, cch + 2, (cch + 2) % 3);
            } else if (cch == 10 && t < kT - 1) {
                load_chunk(t + 1, 0, 0);
            }
            const uint32_t sb = shb + (cch % 3) * STAGE_BYTES;
#pragma unroll
            for (int ks = 0; ks < 2; ks++) {
                const int k0 = ks * 16;
                uint32_t bfr[2][4];
#pragma unroll
                for (int g = 0; g < 2; g++)
                    ldm_x4(bfr[g], sb + (A_ELEMS + (nw * 32 + g * 16 + ldrow) * PITCH + k0 + ldhalf * 8) * 2);
                {
                    uint32_t afr[2][4];
#pragma unroll
                    for (int mi = 0; mi < 2; mi++)
                        ldm_x4(afr[mi], sb + ((0 * BM + mw * 32 + mi * 16 + ldrow) * PITCH + k0 + ldhalf * 8) * 2);
#pragma unroll
                    for (int mi = 0; mi < 2; mi++)
#pragma unroll
                        for (int nj = 0; nj < 4; nj++) {
                            int g = nj >> 1, w = nj & 1;
                            mma16816(acch[mi][nj], afr[mi], bfr[g][w], bfr[g][w + 2]);
                        }
                }
                {
                    uint32_t afr[2][4];
#pragma unroll
                    for (int mi = 0; mi < 2; mi++)
                        ldm_x4(afr[mi], sb + ((1 * BM + mw * 32 + mi * 16 + ldrow) * PITCH + k0 + ldhalf * 8) * 2);
#pragma unroll
                    for (int mi = 0; mi < 2; mi++)
#pragma unroll
                        for (int nj = 0; nj < 4; nj++) {
                            int g = nj >> 1, w = nj & 1;
                            mma16816h(accl[mi][nj], afr[mi], bfr[g][w], bfr[g][w + 2]);
                        }
                }
            }
        }

        // ---- BN + LIF epilogue for timestep t ----
#pragma unroll
        for (int mi = 0; mi < 2; mi++)
#pragma unroll
            for (int nj = 0; nj < 4; nj++) {
                float2 lo0 = __half22float2(*(__half2*)&accl[mi][nj][0]);
                float2 lo1 = __half22float2(*(__half2*)&accl[mi][nj][1]);
                float lov[4] = {lo0.x, lo0.y, lo1.x, lo1.y};
#pragma unroll
                for (int q = 0; q < 4; q++) {
                    const int half = q >> 1;
                    const int j = mi * 16 + nj * 4 + q;
                    float u = (acch[mi][nj][q] + lov[q] * kLoScale - mnv[mi][half]) * scv[mi][half] + bev[mi][half];
                    float vv = vsm[j * 256 + tid];
                    vv += (u - vv) * 0.5f;
                    float s = 0.f;
                    if (vv >= 0.5f) { s = 1.f; vv = 0.f; }
                    vsm[j * 256 + tid] = vv;

                    const int cl = mw * 32 + mi * 16 + half * 8 + gr;
                    const int n = nw * 32 + nj * 8 + gc + (q & 1);
                    if (p == 0) stg[n * QPITCH + cl] = __float2half(s);
                    else        stg[cl * KVP + n]   = __float2half(s);
                }
            }

        __syncthreads();
        if (p == 0) {
#pragma unroll
            for (int it = 0; it < 4; it++) {
                int i = it * 256 + tid;
                int n = i >> 4, w = i & 15;
                uint4 val = *(const uint4*)&stg[n * QPITCH + w * 8];
                *(uint4*)&g_qb[((size_t)((t * kB + b) * kN + n0 + n)) * kC + m0 + w * 8] = val;
            }
        } else {
            const int cl = tid >> 1, h = tid & 1;
            const uint16_t* rp = (const uint16_t*)stg + cl * KVP + h * 32;
            uint32_t m = 0;
#pragma unroll
            for (int jj = 0; jj < 32; jj += 8) {
                uint4 v4 = *(const uint4*)(rp + jj);
                uint32_t w0 = v4.x, w1 = v4.y, w2 = v4.z, w3 = v4.w;
                if (w0 & 0xFFFFu) m |= 1u << (jj + 0);
                if (w0 >> 16)     m |= 1u << (jj + 1);
                if (w1 & 0xFFFFu) m |= 1u << (jj + 2);
                if (w1 >> 16)     m |= 1u << (jj + 3);
                if (w2 & 0xFFFFu) m |= 1u << (jj + 4);
                if (w2 >> 16)     m |= 1u << (jj + 5);
                if (w3 & 0xFFFFu) m |= 1u << (jj + 6);
                if (w3 >> 16)     m |= 1u << (jj + 7);
            }
            uint32_t* dstb = (p == 1) ? g_kbm : g_vbm;
            dstb[((size_t)((t * kB + b) * kC + m0 + cl)) * (kN / 32) + (n0 >> 5) + h] = m;
        }
        __syncthreads();
        if (t < kT - 1) load_chunk(t + 1, 1, 1);
    }
}

// ---------------------------------------------------------------------------
// MERGED kvsum + talking heads + LIF: grid = 8 (one block per b), 512 threads.
// Phase 1: 16 warps popcount this b's 1536 (t,c) rows into smem.
// Phase 2: threads 0..383 run the 8x8 head mix + LIF recurrence from smem.
// Arithmetic identical to the split version (order preserved).
// ---------------------------------------------------------------------------
__global__ void kvred_kernel(const float* __restrict__ th_w) {
    __shared__ float ssum[kT * kC];      // 6144 floats = 24 KB
    __shared__ float th[64];
    const int b = blockIdx.x;
    const int tid = threadIdx.x, wid = tid >> 5, lane = tid & 31;
    if (tid < 64) th[tid] = th_w[tid];

    // phase 1: rows l = t*kC + c, global row = (t*kB+b)*kC + c
    for (int l = wid; l < kT * kC; l += 16) {
        int t = l / kC, c = l - t * kC;
        size_t row = (size_t)((t * kB + b) * kC + c);
        uint32_t kw = g_kbm[row * 32 + lane];
        uint32_t vw = g_vbm[row * 32 + lane];
        int s = __popc(kw & vw);
#pragma unroll
        for (int o = 16; o; o >>= 1) s += __shfl_xor_sync(0xffffffffu, s, o);
        if (lane == 0) ssum[l] = (float)s;
    }
    __syncthreads();

    // phase 2: talking heads + LIF (threads 0..383; d = tid%48 ordering kept)
    if (tid >= 384) return;
    int d = tid % 48;
    int dd = tid / 48;                   // 0..7 -> but original used b = tid/48; here all 8 slices
    // original kernel: thread = (bb, d) with bb = tid/48 over the single block.
    // Here each block owns ONE b; replicate the per-d work across dd slices of d-space:
    // remap: global d' = dd * 48 + d would change ordering; instead keep EXACT original
    // mapping by letting this block's 384 threads cover d in [0,48) x head-slot via:
    // original thread t_orig = bb*48 + d handled (b=bb, d). We now have b fixed, so
    // threads 0..47 (dd==0) do the work; others idle. Cheap: 48 threads x 8 heads.
    if (dd != 0) return;
    float v[8];
#pragma unroll
    for (int o = 0; o < 8; o++) v[o] = 0.0f;
#pragma unroll
    for (int t = 0; t < kT; t++) {
        float kvv[8];
#pragma unroll
        for (int h = 0; h < 8; h++)
            kvv[h] = ssum[t * kC + h * 48 + d];
#pragma unroll
        for (int o = 0; o < 8; o++) {
            float a = 0.0f;
#pragma unroll
            for (int h = 0; h < 8; h++) a += th[o * 8 + h] * kvv[h];
            v[o] += (a - v[o]) * 0.5f;
            float s = 0.f;
            if (v[o] >= 0.5f) { s = 1.f; v[o] = 0.f; }
            g_kvsh[(t * kB + b) * kC + o * 48 + d] = __float2half(s);
        }
    }
}

// ---------------------------------------------------------------------------
// PROJ GEMM (identical to R16): 3-stage, hi split fp32 acc, kvs folded.
// ---------------------------------------------------------------------------
__global__ __launch_bounds__(256, 3) void gemm_proj_kernel(
    const float* __restrict__ pg, const float* __restrict__ pbe,
    const float* __restrict__ pm, const float* __restrict__ pva,
    const float* __restrict__ bias, const float* __restrict__ xres, float* __restrict__ outp)
{
    extern __shared__ __half sh[];
    const uint32_t shb = smem_u32(sh);

    const int tid = threadIdx.x, wid = tid >> 5, lane = tid & 31;
    const int bz = blockIdx.z, t = bz >> 3, b = bz & 7;
    const int m0 = blockIdx.y * BM, n0 = blockIdx.x * BN;

    const __half* Bimg = g_qb + (size_t)(t * kB + b) * kN * kC;
    const uint32_t* kvsp = (const uint32_t*)(g_kvsh + (t * kB + b) * kC);

    const int mw = wid >> 1, nw = wid & 1;

    float acch[2][4][4];
#pragma unroll
    for (int i = 0; i < 2; i++)
#pragma unroll
        for (int j = 0; j < 4; j++)
#pragma unroll
            for (int q = 0; q < 4; q++) acch[i][j][q] = 0.f;

    auto load_chunk = [&](int ck, int st) {
        const uint32_t sb = shb + st * PJSTAGE_BYTES;
        const int k0 = ck * BK;
#pragma unroll
        for (int it = 0; it < 2; it++) {
            int i = it * 256 + tid;
            int r = i >> 2, kq = i & 3;
            cp16(sb + (r * PITCH + kq * 8) * 2,
                 g_wp + (size_t)(m0 + r) * kC + k0 + kq * 8);
        }
        {
            int r = tid >> 2, kq = tid & 3;
            cp16(sb + (PJA_ELEMS + r * PITCH + kq * 8) * 2,
                 Bimg + (size_t)(n0 + r) * kC + k0 + kq * 8);
        }
        asm volatile("cp.async.commit_group;");
    };

    load_chunk(0, 0);
    load_chunk(1, 1);
    const int ldrow = lane & 15, ldhalf = lane >> 4;

    for (int cch = 0; cch < 12; cch++) {
        if (cch == 11) {
            asm volatile("cp.async.wait_group 0;");
        } else {
            asm volatile("cp.async.wait_group 1;");
        }
        __syncthreads();
        if (cch <= 9) load_chunk(cch + 2, (cch + 2) % 3);
        const uint32_t sb = shb + (cch % 3) * PJSTAGE_BYTES;
#pragma unroll
        for (int ks = 0; ks < 2; ks++) {
            const int k0 = ks * 16;
            uint32_t bfr[2][4];
#pragma unroll
            for (int g = 0; g < 2; g++)
                ldm_x4(bfr[g], sb + (PJA_ELEMS + (nw * 32 + g * 16 + ldrow) * PITCH + k0 + ldhalf * 8) * 2);
            {
                uint32_t p0 = kvsp[cch * 16 + ks * 8 + (lane & 3)];
                uint32_t p1 = kvsp[cch * 16 + ks * 8 + 4 + (lane & 3)];
#pragma unroll
                for (int g = 0; g < 2; g++) {
                    bfr[g][0] = hmul2u(bfr[g][0], p0);
                    bfr[g][1] = hmul2u(bfr[g][1], p0);
                    bfr[g][2] = hmul2u(bfr[g][2], p1);
                    bfr[g][3] = hmul2u(bfr[g][3], p1);
                }
            }
            uint32_t afr[2][4];
#pragma unroll
            for (int mi = 0; mi < 2; mi++)
                ldm_x4(afr[mi], sb + ((mw * 32 + mi * 16 + ldrow) * PITCH + k0 + ldhalf * 8) * 2);
#pragma unroll
            for (int mi = 0; mi < 2; mi++)
#pragma unroll
                for (int nj = 0; nj < 4; nj++) {
                    int g = nj >> 1, w = nj & 1;
                    mma16816(acch[mi][nj], afr[mi], bfr[g][w], bfr[g][w + 2]);
                }
        }
    }

    const int gr = lane >> 2, gc = (lane & 3) * 2;
    const size_t imgoff = ((size_t)(t * kB + b) * kC) * kN;

#pragma unroll
    for (int mi = 0; mi < 2; mi++) {
#pragma unroll
        for (int half = 0; half < 2; half++) {
            const int c = m0 + mw * 32 + mi * 16 + gr + half * 8;
            const float sc = pg[c] / sqrtf(pva[c] + kEPS);
            const float mn = pm[c], be = pbe[c];
            const float bi = bias[c];
            size_t rowoff = imgoff + (size_t)c * kN;
            float* dst = outp + rowoff;
#pragma unroll
            for (int nj = 0; nj < 4; nj++) {
                const int n = n0 + nw * 32 + nj * 8 + gc;
                float v0 = acch[mi][nj][half * 2 + 0];
                float v1 = acch[mi][nj][half * 2 + 1];
                float2 xv = *(const float2*)(xres + rowoff + n);
                float2 o;
                o.x = ((v0 + bi) - mn) * sc + be + xv.x;
                o.y = ((v1 + bi) - mn) * sc + be + xv.y;
                *(float2*)(dst + n) = o;
            }
        }
    }
}

// ---------------------------------------------------------------------------
extern "C" void kernel_launch(void* const* d_in, const int* in_sizes, int n_in,
                              void* d_out, int out_size)
{
    const float* x   = (const float*)d_in[0];
    const float* qw  = (const float*)d_in[1];
    const float* kw  = (const float*)d_in[2];
    const float* vw  = (const float*)d_in[3];
    const float* thw = (const float*)d_in[4];
    const float* pw  = (const float*)d_in[5];
    const float* pb  = (const float*)d_in[6];
    const float* qg  = (const float*)d_in[7];
    const float* qbe = (const float*)d_in[8];
    const float* qm  = (const float*)d_in[9];
    const float* qva = (const float*)d_in[10];
    const float* kg  = (const float*)d_in[11];
    const float* kbe = (const float*)d_in[12];
    const float* km  = (const float*)d_in[13];
    const float* kva = (const float*)d_in[14];
    const float* vg  = (const float*)d_in[15];
    const float* vbe = (const float*)d_in[16];
    const float* vm  = (const float*)d_in[17];
    const float* vva = (const float*)d_in[18];
    const float* pg  = (const float*)d_in[19];
    const float* pbe = (const float*)d_in[20];
    const float* pm  = (const float*)d_in[21];
    const float* pva = (const float*)d_in[22];
    float* out = (float*)d_out;

    cudaFuncSetAttribute(fused_qkv_kernel, cudaFuncAttributeMaxDynamicSharedMemorySize, FSMEM);
    cudaFuncSetAttribute(gemm_proj_kernel, cudaFuncAttributeMaxDynamicSharedMemorySize, PJSMEM);

    lif_x_split_kernel<<<dim3(kN / 32, kC / 32, kB + 6), 256>>>(x, qw, kw, vw, pw);

    fused_qkv_kernel<<<dim3(kN / BN, 9, kB), 256, FSMEM>>>(
        qg, qbe, qm, qva, kg, kbe, km, kva, vg, vbe, vm, vva);

    kvred_kernel<<<kB, 512>>>(thw);

    gemm_proj_kernel<<<dim3(kN / BN, kC / BM, kT * kB), 256, PJSMEM>>>(
        pg, pbe, pm, pva, pb, x, out);
}